// round 3
// baseline (speedup 1.0000x reference)
#include <cuda_runtime.h>
#include <cstdint>

// Problem constants (GCN_59846074302981): N=50000, E=800000, F=H=128, C=8
#define MAX_N 50000
#define MAX_E 800000

// ---------------------------------------------------------------------------
// Scratch (allocation-free: device globals, referenced directly from kernels)
// ---------------------------------------------------------------------------
__device__ __align__(16) float g_bufA[MAX_N * 128];  // GEMM out / agg in
__device__ __align__(16) float g_bufB[MAX_N * 128];  // agg out / next GEMM in
__device__ __align__(16) float g_dinv[MAX_N];
__device__ __align__(16) float g_w[MAX_E];           // edge norm per CSR slot
__device__ int   g_count[MAX_N];                     // histogram, then fill cursor
__device__ int   g_off[MAX_N + 1];                   // CSR offsets (by dest col)
__device__ int   g_srcIdx[MAX_E];                    // source node per CSR slot
__device__ int   g_stride;                           // 1 = int32 edge data, 2 = int64

// ---------------------------------------------------------------------------
// Edge-index dtype detection: view buffer as int32 words. int64 data with
// indices < 2^31 has every odd word == 0; int32 data essentially never does.
// ---------------------------------------------------------------------------
__global__ void k_detect(const int* __restrict__ buf) {
    if (threadIdx.x == 0 && blockIdx.x == 0) {
        int is64 = 1;
        #pragma unroll 1
        for (int i = 0; i < 256; i++)
            if (buf[2 * i + 1] != 0) { is64 = 0; break; }
        g_stride = is64 ? 2 : 1;
    }
}

// Read element j of the flattened (2E,) index array regardless of dtype.
__device__ __forceinline__ int edge_at(const int* __restrict__ buf, int j, int stride) {
    return buf[(long)j * stride];
}

// ---------------------------------------------------------------------------
// CSR build pipeline
// ---------------------------------------------------------------------------
__global__ void k_zero_counts(int n) {
    int i = blockIdx.x * blockDim.x + threadIdx.x;
    if (i < n) g_count[i] = 0;
}

__global__ void k_hist(const int* __restrict__ ebuf, int e, int n) {
    int i = blockIdx.x * blockDim.x + threadIdx.x;
    if (i >= e) return;
    int st = g_stride;
    int c = edge_at(ebuf, e + i, st);   // col section starts at element e
    if ((unsigned)c < (unsigned)n) atomicAdd(&g_count[c], 1);
}

__global__ void k_dinv(int n) {
    int i = blockIdx.x * blockDim.x + threadIdx.x;
    if (i < n) g_dinv[i] = rsqrtf((float)g_count[i] + 1.0f);  // +1 self-loop
}

// Single-block exclusive scan: g_count[0..n) -> g_off[0..n], strip-per-thread.
__global__ __launch_bounds__(1024) void k_scan(int n) {
    const int T = 1024;
    int tid  = threadIdx.x;
    int L    = (n + T - 1) / T;
    int beg  = tid * L;
    int end  = beg + L; if (end > n) end = n;

    int s = 0;
    for (int i = beg; i < end; i++) s += g_count[i];

    __shared__ int wsum[32];
    int lane = tid & 31, wid = tid >> 5;
    int v = s;
    #pragma unroll
    for (int o = 1; o < 32; o <<= 1) {
        int t = __shfl_up_sync(0xffffffffu, v, o);
        if (lane >= o) v += t;
    }
    if (lane == 31) wsum[wid] = v;
    __syncthreads();
    if (wid == 0) {
        int w = wsum[lane];
        #pragma unroll
        for (int o = 1; o < 32; o <<= 1) {
            int t = __shfl_up_sync(0xffffffffu, w, o);
            if (lane >= o) w += t;
        }
        wsum[lane] = w;
    }
    __syncthreads();

    int excl = v - s + (wid ? wsum[wid - 1] : 0);
    int run = excl;
    for (int i = beg; i < end; i++) { g_off[i] = run; run += g_count[i]; }
    if (tid == T - 1) g_off[n] = run;   // last strip empty-or-final: run == total
}

__global__ void k_fill(const int* __restrict__ ebuf, int e, int n) {
    int i = blockIdx.x * blockDim.x + threadIdx.x;
    if (i >= e) return;
    int st = g_stride;
    int r = edge_at(ebuf, i, st);
    int c = edge_at(ebuf, e + i, st);
    if ((unsigned)r >= (unsigned)n || (unsigned)c >= (unsigned)n) return;
    int slot = g_off[c] + atomicAdd(&g_count[c], 1);
    g_srcIdx[slot] = r;
    g_w[slot] = g_dinv[r] * g_dinv[c];
}

// ---------------------------------------------------------------------------
// GEMM: g_bufA[n,128] = SRC[n,128] @ W[128,128]
// SRC = Xext if use_ext else g_bufB. fp32 SIMT, 64x128 tile, 256 thr, 4x8/thr.
// ---------------------------------------------------------------------------
__global__ __launch_bounds__(256) void k_gemm128(const float* __restrict__ Xext,
                                                 const float* __restrict__ W,
                                                 int use_ext, int nrows) {
    const float* __restrict__ X = use_ext ? Xext : g_bufB;
    __shared__ __align__(16) float xs[32][64 + 4];   // [k][m], padded
    __shared__ __align__(16) float ws[32][128];      // [k][n]

    const int row0 = blockIdx.x * 64;
    const int tid  = threadIdx.x;
    const int tm   = (tid >> 4) << 2;   // 0..60 step 4
    const int tn   = (tid & 15) << 3;   // 0..120 step 8

    float acc[4][8];
    #pragma unroll
    for (int i = 0; i < 4; i++)
        #pragma unroll
        for (int j = 0; j < 8; j++) acc[i][j] = 0.0f;

    for (int kk = 0; kk < 128; kk += 32) {
        #pragma unroll
        for (int i = 0; i < 2; i++) {
            int s  = tid + i * 256;      // 0..511
            int r  = s >> 3;             // 0..63
            int c4 = s & 7;              // float4 slot within 32-wide K chunk
            float4 v = make_float4(0.f, 0.f, 0.f, 0.f);
            if (row0 + r < nrows)
                v = reinterpret_cast<const float4*>(X)[(long)(row0 + r) * 32 + (kk >> 2) + c4];
            int kb = c4 << 2;
            xs[kb + 0][r] = v.x; xs[kb + 1][r] = v.y;
            xs[kb + 2][r] = v.z; xs[kb + 3][r] = v.w;
        }
        #pragma unroll
        for (int i = 0; i < 4; i++) {
            int s  = tid + i * 256;      // 0..1023
            int k  = s >> 5;             // 0..31
            int c4 = s & 31;
            reinterpret_cast<float4*>(ws[k])[c4] =
                reinterpret_cast<const float4*>(W)[(kk + k) * 32 + c4];
        }
        __syncthreads();

        #pragma unroll
        for (int k = 0; k < 32; k++) {
            float a[4] = {xs[k][tm + 0], xs[k][tm + 1], xs[k][tm + 2], xs[k][tm + 3]};
            float4 b0 = reinterpret_cast<const float4*>(ws[k])[(tn >> 2) + 0];
            float4 b1 = reinterpret_cast<const float4*>(ws[k])[(tn >> 2) + 1];
            float b[8] = {b0.x, b0.y, b0.z, b0.w, b1.x, b1.y, b1.z, b1.w};
            #pragma unroll
            for (int i = 0; i < 4; i++)
                #pragma unroll
                for (int j = 0; j < 8; j++)
                    acc[i][j] += a[i] * b[j];
        }
        __syncthreads();
    }

    #pragma unroll
    for (int i = 0; i < 4; i++) {
        int r = row0 + tm + i;
        if (r < nrows) {
            reinterpret_cast<float4*>(g_bufA)[(long)r * 32 + (tn >> 2) + 0] =
                make_float4(acc[i][0], acc[i][1], acc[i][2], acc[i][3]);
            reinterpret_cast<float4*>(g_bufA)[(long)r * 32 + (tn >> 2) + 1] =
                make_float4(acc[i][4], acc[i][5], acc[i][6], acc[i][7]);
        }
    }
}

// ---------------------------------------------------------------------------
// Aggregation (atomic-free): one warp per node, lane owns one float4 of H=128.
// g_bufB[node] = bias + dinv^2 * g_bufA[node] + sum_{e->node} w_e * g_bufA[src_e]
// ---------------------------------------------------------------------------
__global__ __launch_bounds__(256) void k_aggregate(const float* __restrict__ bias, int n) {
    int warp = blockIdx.x * (blockDim.x >> 5) + (threadIdx.x >> 5);
    int lane = threadIdx.x & 31;
    if (warp >= n) return;

    const float4* __restrict__ h4 = reinterpret_cast<const float4*>(g_bufA);

    float d = g_dinv[warp];
    float s = d * d;
    float4 b  = reinterpret_cast<const float4*>(bias)[lane];
    float4 hv = h4[(long)warp * 32 + lane];
    float ax = b.x + s * hv.x, ay = b.y + s * hv.y;
    float az = b.z + s * hv.z, aw = b.w + s * hv.w;

    int j   = g_off[warp];
    int end = g_off[warp + 1];

    for (; j + 1 < end; j += 2) {
        int   r0 = g_srcIdx[j],     r1 = g_srcIdx[j + 1];
        float w0 = g_w[j],          w1 = g_w[j + 1];
        float4 v0 = h4[(long)r0 * 32 + lane];
        float4 v1 = h4[(long)r1 * 32 + lane];
        ax += w0 * v0.x; ay += w0 * v0.y; az += w0 * v0.z; aw += w0 * v0.w;
        ax += w1 * v1.x; ay += w1 * v1.y; az += w1 * v1.z; aw += w1 * v1.w;
    }
    if (j < end) {
        int   r0 = g_srcIdx[j];
        float w0 = g_w[j];
        float4 v0 = h4[(long)r0 * 32 + lane];
        ax += w0 * v0.x; ay += w0 * v0.y; az += w0 * v0.z; aw += w0 * v0.w;
    }

    reinterpret_cast<float4*>(g_bufB)[(long)warp * 32 + lane] = make_float4(ax, ay, az, aw);
}

// ---------------------------------------------------------------------------
// Final FC: out[n,8] = g_bufB[n,128] @ Wfc[128,8] + bfc
// ---------------------------------------------------------------------------
__global__ __launch_bounds__(256) void k_fc(const float* __restrict__ Wfc,
                                            const float* __restrict__ bfc,
                                            float* __restrict__ out, int nrows) {
    __shared__ __align__(16) float xs[32][129];
    __shared__ __align__(16) float ws[128 * 8];
    __shared__ float bs[8];

    int row0 = blockIdx.x * 32;
    int tid  = threadIdx.x;

    reinterpret_cast<float4*>(ws)[tid] = reinterpret_cast<const float4*>(Wfc)[tid];
    if (tid < 8) bs[tid] = bfc[tid];

    #pragma unroll
    for (int i = 0; i < 4; i++) {
        int s  = tid + i * 256;   // 0..1023
        int r  = s >> 5;          // 0..31
        int c4 = s & 31;
        float4 v = make_float4(0.f, 0.f, 0.f, 0.f);
        if (row0 + r < nrows)
            v = reinterpret_cast<const float4*>(g_bufB)[(long)(row0 + r) * 32 + c4];
        int cb = c4 << 2;
        xs[r][cb + 0] = v.x; xs[r][cb + 1] = v.y;
        xs[r][cb + 2] = v.z; xs[r][cb + 3] = v.w;
    }
    __syncthreads();

    int r = tid >> 3, c = tid & 7;
    float acc = 0.0f;
    #pragma unroll 16
    for (int k = 0; k < 128; k++)
        acc += xs[r][k] * ws[k * 8 + c];

    if (row0 + r < nrows)
        out[(long)(row0 + r) * 8 + c] = acc + bs[c];
}

// ---------------------------------------------------------------------------
// Launcher
// ---------------------------------------------------------------------------
extern "C" void kernel_launch(void* const* d_in, const int* in_sizes, int n_in,
                              void* d_out, int out_size) {
    const float* x   = (const float*)d_in[0];
    const int*   ei  = (const int*)d_in[1];   // int32 view; stride handles int64
    const float* W1  = (const float*)d_in[2];
    const float* b1  = (const float*)d_in[3];
    const float* W2  = (const float*)d_in[4];
    const float* b2  = (const float*)d_in[5];
    const float* Wfc = (const float*)d_in[6];
    const float* bfc = (const float*)d_in[7];
    float*       out = (float*)d_out;

    const int n = in_sizes[0] / 128;
    const int e = in_sizes[1] / 2;   // element count of edge_index is dtype-independent

    const int T = 256;
    int gn  = (n + T - 1) / T;
    int ge  = (e + T - 1) / T;
    int gg  = (n + 63) / 64;
    int gag = (n + 7) / 8;          // 8 warps per block
    int gfc = (n + 31) / 32;

    // 0) dtype probe
    k_detect<<<1, 32>>>(ei);

    // 1) CSR build + normalization
    k_zero_counts<<<gn, T>>>(n);
    k_hist<<<ge, T>>>(ei, e, n);
    k_dinv<<<gn, T>>>(n);
    k_scan<<<1, 1024>>>(n);
    k_zero_counts<<<gn, T>>>(n);                 // reuse as fill cursor
    k_fill<<<ge, T>>>(ei, e, n);

    // 2) layer 1
    k_gemm128<<<gg, T>>>(x, W1, 1, n);           // bufA = x @ W1
    k_aggregate<<<gag, T>>>(b1, n);              // bufB = agg(bufA) + b1

    // 3) layer 2
    k_gemm128<<<gg, T>>>(nullptr, W2, 0, n);     // bufA = bufB @ W2
    k_aggregate<<<gag, T>>>(b2, n);              // bufB = agg(bufA) + b2

    // 4) classifier
    k_fc<<<gfc, T>>>(Wfc, bfc, out, n);
}